// round 9
// baseline (speedup 1.0000x reference)
#include <cuda_runtime.h>
#include <cuda_bf16.h>
#include <cstdint>

// Problem constants (match reference)
#define NPTS 200000
#define BATCH 4
#define CV 64
#define CI 256
#define HF 48
#define WF 160
#define HW (HF * WF)          // 7680
#define OUTW (CV + CI)        // 320

#define TR_BLOCKS 1920                      // 60 * 8 * 4 transpose tiles
#define VOX_BLOCKS 3125                     // voxel copy: 3.2M float4 / 1024
#define META_BLOCKS ((NPTS + 255) / 256)    // 782
#define PTS_PER_BLOCK 16                    // gather: 8 warps x 2 points

// Scratch: img_feats transposed to [B, H, W, C] (channels contiguous).
// 31.4 MB — L2-resident (L2 ~126 MB).
__device__ float g_imgT[(size_t)BATCH * HW * CI];
// Per-point gather metadata: corner element offsets into g_imgT (0 if
// invalid -> reads the L1-hot line at g_imgT[0], weighted by 0) and the 4
// bilinear weights (0 if invalid).
__device__ int4   g_off[NPTS];
__device__ float4 g_w[NPTS];

// ---------------------------------------------------------------------------
// Transpose tile body: [B, C, H*W] -> [B, H*W, C], float4 both global sides.
// ---------------------------------------------------------------------------
__device__ __forceinline__ void transpose_tile(const float* __restrict__ img,
                                               int tileId, int t) {
    __shared__ float tile[32][129];
    const int px = tileId % 60;
    const int cy = (tileId / 60) % 8;
    const int b  = tileId / 480;
    const int p0 = px * 128;
    const int c0 = cy * 32;

    const float* src = img    + (size_t)b * CI * HW;
    float*       dst = g_imgT + (size_t)b * HW * CI;

    float4 v[4];
    int cc[4], qq[4];
    #pragma unroll
    for (int r = 0; r < 4; r++) {
        const int linear = r * 256 + t;
        cc[r] = linear >> 5;
        qq[r] = linear & 31;
        v[r] = *(const float4*)(src + (size_t)(c0 + cc[r]) * HW + p0 + qq[r] * 4);
    }
    #pragma unroll
    for (int r = 0; r < 4; r++) {
        tile[cc[r]][qq[r] * 4 + 0] = v[r].x;
        tile[cc[r]][qq[r] * 4 + 1] = v[r].y;
        tile[cc[r]][qq[r] * 4 + 2] = v[r].z;
        tile[cc[r]][qq[r] * 4 + 3] = v[r].w;
    }
    __syncthreads();

    #pragma unroll
    for (int r = 0; r < 4; r++) {
        const int linear = r * 256 + t;
        const int p  = linear >> 3;
        const int cq = linear & 7;
        float4 o;
        o.x = tile[cq * 4 + 0][p];
        o.y = tile[cq * 4 + 1][p];
        o.z = tile[cq * 4 + 2][p];
        o.w = tile[cq * 4 + 3][p];
        *(float4*)(dst + (size_t)(p0 + p) * CI + c0 + cq * 4) = o;
    }
}

// ---------------------------------------------------------------------------
// Voxel copy body: voxel_feats row -> first 64 floats of out row.
// ---------------------------------------------------------------------------
__device__ __forceinline__ void voxel_copy(const float* __restrict__ voxel_feats,
                                           float* __restrict__ out,
                                           int blockId, int t) {
    const float4* src = (const float4*)voxel_feats;
    #pragma unroll
    for (int r = 0; r < 4; r++) {
        const int idx = blockId * 1024 + r * 256 + t;   // < 3.2M
        const int n = idx >> 4;
        const int q = idx & 15;
        float4 v = __ldcs(&src[idx]);
        __stcs((float4*)(out + (size_t)n * OUTW) + q, v);
    }
}

// ---------------------------------------------------------------------------
// Meta body: per-point projection, ONE thread per point.
// ---------------------------------------------------------------------------
__device__ __forceinline__ void meta_point(const float* __restrict__ points_mean,
                                           const int*   __restrict__ coors,
                                           const float* __restrict__ lidar2img,
                                           const int*   __restrict__ pad_shape,
                                           int n) {
    const int b = __ldg(&coors[(size_t)n * 4]);

    const float px = __ldg(&points_mean[(size_t)n * 3 + 0]);
    const float py = __ldg(&points_mean[(size_t)n * 3 + 1]);
    const float pz = __ldg(&points_mean[(size_t)n * 3 + 2]);

    const float* M = lidar2img + (size_t)b * 16;
    const float p0 = __ldg(&M[0]) * px + __ldg(&M[1]) * py + __ldg(&M[2])  * pz + __ldg(&M[3]);
    const float p1 = __ldg(&M[4]) * px + __ldg(&M[5]) * py + __ldg(&M[6])  * pz + __ldg(&M[7]);
    const float p2 = __ldg(&M[8]) * px + __ldg(&M[9]) * py + __ldg(&M[10]) * pz + __ldg(&M[11]);

    const float z     = fmaxf(p2, 1e-5f);
    const float x_pix = p0 / z;
    const float y_pix = p1 / z;

    const float padH = (float)__ldg(&pad_shape[(size_t)b * 2 + 0]);
    const float padW = (float)__ldg(&pad_shape[(size_t)b * 2 + 1]);

    const float gx = x_pix / padW * 2.0f - 1.0f;
    const float gy = y_pix / padH * 2.0f - 1.0f;
    const float ix = (gx + 1.0f) * 0.5f * (float)(WF - 1);
    const float iy = (gy + 1.0f) * 0.5f * (float)(HF - 1);

    const float ix0f = floorf(ix);
    const float iy0f = floorf(iy);
    const float wx1 = ix - ix0f, wx0 = 1.0f - wx1;
    const float wy1 = iy - iy0f, wy0 = 1.0f - wy1;

    const int ix0 = (int)ix0f, iy0 = (int)iy0f;
    const int ix1 = ix0 + 1,   iy1 = iy0 + 1;

    const bool vx0 = (ix0 >= 0) & (ix0 < WF);
    const bool vx1 = (ix1 >= 0) & (ix1 < WF);
    const bool vy0 = (iy0 >= 0) & (iy0 < HF);
    const bool vy1 = (iy1 >= 0) & (iy1 < HF);

    const float w00 = (vy0 & vx0) ? (wy0 * wx0) : 0.0f;
    const float w01 = (vy0 & vx1) ? (wy0 * wx1) : 0.0f;
    const float w10 = (vy1 & vx0) ? (wy1 * wx0) : 0.0f;
    const float w11 = (vy1 & vx1) ? (wy1 * wx1) : 0.0f;

    const int bbase = b * HW * CI;
    int4 off;
    off.x = (w00 != 0.0f) ? bbase + (iy0 * WF + ix0) * CI : 0;
    off.y = (w01 != 0.0f) ? bbase + (iy0 * WF + ix1) * CI : 0;
    off.z = (w10 != 0.0f) ? bbase + (iy1 * WF + ix0) * CI : 0;
    off.w = (w11 != 0.0f) ? bbase + (iy1 * WF + ix1) * CI : 0;

    g_off[n] = off;
    g_w[n]   = make_float4(w00, w01, w10, w11);
}

// ---------------------------------------------------------------------------
// Kernel A: fused transpose + voxel copy + meta (all independent work).
// ---------------------------------------------------------------------------
__global__ __launch_bounds__(256)
void prep_kernel(const float* __restrict__ img,
                 const float* __restrict__ points_mean,
                 const int*   __restrict__ coors,
                 const float* __restrict__ lidar2img,
                 const int*   __restrict__ pad_shape,
                 const float* __restrict__ voxel_feats,
                 float*       __restrict__ out) {
    if (blockIdx.x < TR_BLOCKS) {
        transpose_tile(img, blockIdx.x, threadIdx.x);
    } else if (blockIdx.x < TR_BLOCKS + VOX_BLOCKS) {
        voxel_copy(voxel_feats, out, blockIdx.x - TR_BLOCKS, threadIdx.x);
    } else {
        const int n = (blockIdx.x - TR_BLOCKS - VOX_BLOCKS) * 256 + threadIdx.x;
        if (n < NPTS)
            meta_point(points_mean, coors, lidar2img, pad_shape, n);
    }
}

// BRANCHLESS corner accumulate: always load (invalid corners read the
// L1-hot line at g_imgT[0]) and FMA with w (0 for invalid). Straight-line
// code lets ptxas front-batch all corner LDG.128s -> high MLP.
__device__ __forceinline__ void corner_acc(int off, float w,
                                           int off0, int off1,
                                           float4& a0, float4& a1) {
    const float* row = g_imgT + off;
    float4 v0 = *(const float4*)(row + off0);
    float4 v1 = *(const float4*)(row + off1);
    a0.x = fmaf(w, v0.x, a0.x); a0.y = fmaf(w, v0.y, a0.y);
    a0.z = fmaf(w, v0.z, a0.z); a0.w = fmaf(w, v0.w, a0.w);
    a1.x = fmaf(w, v1.x, a1.x); a1.y = fmaf(w, v1.y, a1.y);
    a1.z = fmaf(w, v1.z, a1.z); a1.w = fmaf(w, v1.w, a1.w);
}

// ---------------------------------------------------------------------------
// Kernel B: gather + point-feat write (voxel handled in prep).
// Block (8 warps) owns 16 points; warp owns 2 (unrolled). Meta staged in
// smem. Branchless corner gathers -> all 16 LDG.128s per warp independent.
// ---------------------------------------------------------------------------
__global__ __launch_bounds__(256)
void gather_kernel(float* __restrict__ out) {
    __shared__ int4   s_off[PTS_PER_BLOCK];
    __shared__ float4 s_w[PTS_PER_BLOCK];

    const int t    = threadIdx.x;
    const int base = blockIdx.x * PTS_PER_BLOCK;

    if (t < PTS_PER_BLOCK) {
        s_off[t] = __ldg(&g_off[base + t]);
    } else if (t < 2 * PTS_PER_BLOCK) {
        s_w[t - PTS_PER_BLOCK] = __ldg(&g_w[base + t - PTS_PER_BLOCK]);
    }
    __syncthreads();

    const int warp = t >> 5;   // 0..7
    const int lane = t & 31;
    const int off0 = lane * 4;
    const int off1 = 128 + lane * 4;

    #pragma unroll
    for (int i = 0; i < 2; i++) {
        const int li = warp * 2 + i;   // 0..15
        const int n  = base + li;      // NPTS % 16 == 0 -> in bounds

        const int4   off = s_off[li];  // LDS broadcast
        const float4 w   = s_w[li];

        float4 a0 = make_float4(0.f, 0.f, 0.f, 0.f);
        float4 a1 = make_float4(0.f, 0.f, 0.f, 0.f);

        corner_acc(off.x, w.x, off0, off1, a0, a1);
        corner_acc(off.y, w.y, off0, off1, a0, a1);
        corner_acc(off.z, w.z, off0, off1, a0, a1);
        corner_acc(off.w, w.w, off0, off1, a0, a1);

        float4* orow = (float4*)(out + (size_t)n * OUTW);
        __stcs(&orow[16 + lane],      a0);
        __stcs(&orow[16 + 32 + lane], a1);
    }
}

// ---------------------------------------------------------------------------
extern "C" void kernel_launch(void* const* d_in, const int* in_sizes, int n_in,
                              void* d_out, int out_size) {
    const float* points_mean = (const float*)d_in[0];
    // d_in[1] = mask (unused by reference)
    const float* voxel_feats = (const float*)d_in[2];
    const int*   coors       = (const int*)  d_in[3];
    const float* img_feats   = (const float*)d_in[4];
    const float* lidar2img   = (const float*)d_in[5];
    const int*   pad_shape   = (const int*)  d_in[6];
    float*       out         = (float*)d_out;

    // A: fused transpose + voxel copy + projection meta
    prep_kernel<<<TR_BLOCKS + VOX_BLOCKS + META_BLOCKS, 256>>>(
        img_feats, points_mean, coors, lidar2img, pad_shape, voxel_feats, out);

    // B: gather + point-feat write (block = 16 points)
    gather_kernel<<<NPTS / PTS_PER_BLOCK, 256>>>(out);
}

// round 10
// speedup vs baseline: 1.1282x; 1.1282x over previous
#include <cuda_runtime.h>
#include <cuda_bf16.h>
#include <cstdint>

// Problem constants (match reference)
#define NPTS 200000
#define BATCH 4
#define CV 64
#define CI 256
#define HF 48
#define WF 160
#define HW (HF * WF)          // 7680
#define OUTW (CV + CI)        // 320

#define TR_BLOCKS 1920                      // 60 * 8 * 4 transpose tiles
#define VOX_BLOCKS 3125                     // voxel copy: 3.2M float4 / 1024
#define META_BLOCKS ((NPTS + 255) / 256)    // 782
#define PTS_PER_BLOCK 16                    // gather: 8 warps x 2 points

// Scratch: img_feats transposed to [B, H, W, C] (channels contiguous).
// 31.4 MB — L2-resident (L2 ~126 MB).
__device__ float g_imgT[(size_t)BATCH * HW * CI];
// Per-point gather metadata: corner element offsets into g_imgT (0 if
// invalid) and the 4 bilinear weights (0 if invalid).
__device__ int4   g_off[NPTS];
__device__ float4 g_w[NPTS];

// ---------------------------------------------------------------------------
// Transpose tile body: [B, C, H*W] -> [B, H*W, C], float4 both global sides.
// Source read with __ldcs (read-once; keep L2 for g_imgT).
// ---------------------------------------------------------------------------
__device__ __forceinline__ void transpose_tile(const float* __restrict__ img,
                                               int tileId, int t) {
    __shared__ float tile[32][129];
    const int px = tileId % 60;
    const int cy = (tileId / 60) % 8;
    const int b  = tileId / 480;
    const int p0 = px * 128;
    const int c0 = cy * 32;

    const float* src = img    + (size_t)b * CI * HW;
    float*       dst = g_imgT + (size_t)b * HW * CI;

    float4 v[4];
    int cc[4], qq[4];
    #pragma unroll
    for (int r = 0; r < 4; r++) {
        const int linear = r * 256 + t;
        cc[r] = linear >> 5;
        qq[r] = linear & 31;
        v[r] = __ldcs((const float4*)(src + (size_t)(c0 + cc[r]) * HW + p0 + qq[r] * 4));
    }
    #pragma unroll
    for (int r = 0; r < 4; r++) {
        tile[cc[r]][qq[r] * 4 + 0] = v[r].x;
        tile[cc[r]][qq[r] * 4 + 1] = v[r].y;
        tile[cc[r]][qq[r] * 4 + 2] = v[r].z;
        tile[cc[r]][qq[r] * 4 + 3] = v[r].w;
    }
    __syncthreads();

    #pragma unroll
    for (int r = 0; r < 4; r++) {
        const int linear = r * 256 + t;
        const int p  = linear >> 3;
        const int cq = linear & 7;
        float4 o;
        o.x = tile[cq * 4 + 0][p];
        o.y = tile[cq * 4 + 1][p];
        o.z = tile[cq * 4 + 2][p];
        o.w = tile[cq * 4 + 3][p];
        *(float4*)(dst + (size_t)(p0 + p) * CI + c0 + cq * 4) = o;
    }
}

// ---------------------------------------------------------------------------
// Voxel copy body: voxel_feats row -> first 64 floats of out row.
// ---------------------------------------------------------------------------
__device__ __forceinline__ void voxel_copy(const float* __restrict__ voxel_feats,
                                           float* __restrict__ out,
                                           int blockId, int t) {
    const float4* src = (const float4*)voxel_feats;
    #pragma unroll
    for (int r = 0; r < 4; r++) {
        const int idx = blockId * 1024 + r * 256 + t;   // < 3.2M
        const int n = idx >> 4;
        const int q = idx & 15;
        float4 v = __ldcs(&src[idx]);
        __stcs((float4*)(out + (size_t)n * OUTW) + q, v);
    }
}

// ---------------------------------------------------------------------------
// Meta body: per-point projection, ONE thread per point.
// ---------------------------------------------------------------------------
__device__ __forceinline__ void meta_point(const float* __restrict__ points_mean,
                                           const int*   __restrict__ coors,
                                           const float* __restrict__ lidar2img,
                                           const int*   __restrict__ pad_shape,
                                           int n) {
    const int b = __ldg(&coors[(size_t)n * 4]);

    const float px = __ldg(&points_mean[(size_t)n * 3 + 0]);
    const float py = __ldg(&points_mean[(size_t)n * 3 + 1]);
    const float pz = __ldg(&points_mean[(size_t)n * 3 + 2]);

    const float* M = lidar2img + (size_t)b * 16;
    const float p0 = __ldg(&M[0]) * px + __ldg(&M[1]) * py + __ldg(&M[2])  * pz + __ldg(&M[3]);
    const float p1 = __ldg(&M[4]) * px + __ldg(&M[5]) * py + __ldg(&M[6])  * pz + __ldg(&M[7]);
    const float p2 = __ldg(&M[8]) * px + __ldg(&M[9]) * py + __ldg(&M[10]) * pz + __ldg(&M[11]);

    const float z     = fmaxf(p2, 1e-5f);
    const float x_pix = p0 / z;
    const float y_pix = p1 / z;

    const float padH = (float)__ldg(&pad_shape[(size_t)b * 2 + 0]);
    const float padW = (float)__ldg(&pad_shape[(size_t)b * 2 + 1]);

    const float gx = x_pix / padW * 2.0f - 1.0f;
    const float gy = y_pix / padH * 2.0f - 1.0f;
    const float ix = (gx + 1.0f) * 0.5f * (float)(WF - 1);
    const float iy = (gy + 1.0f) * 0.5f * (float)(HF - 1);

    const float ix0f = floorf(ix);
    const float iy0f = floorf(iy);
    const float wx1 = ix - ix0f, wx0 = 1.0f - wx1;
    const float wy1 = iy - iy0f, wy0 = 1.0f - wy1;

    const int ix0 = (int)ix0f, iy0 = (int)iy0f;
    const int ix1 = ix0 + 1,   iy1 = iy0 + 1;

    const bool vx0 = (ix0 >= 0) & (ix0 < WF);
    const bool vx1 = (ix1 >= 0) & (ix1 < WF);
    const bool vy0 = (iy0 >= 0) & (iy0 < HF);
    const bool vy1 = (iy1 >= 0) & (iy1 < HF);

    const float w00 = (vy0 & vx0) ? (wy0 * wx0) : 0.0f;
    const float w01 = (vy0 & vx1) ? (wy0 * wx1) : 0.0f;
    const float w10 = (vy1 & vx0) ? (wy1 * wx0) : 0.0f;
    const float w11 = (vy1 & vx1) ? (wy1 * wx1) : 0.0f;

    const int bbase = b * HW * CI;
    int4 off;
    off.x = (w00 != 0.0f) ? bbase + (iy0 * WF + ix0) * CI : 0;
    off.y = (w01 != 0.0f) ? bbase + (iy0 * WF + ix1) * CI : 0;
    off.z = (w10 != 0.0f) ? bbase + (iy1 * WF + ix0) * CI : 0;
    off.w = (w11 != 0.0f) ? bbase + (iy1 * WF + ix1) * CI : 0;

    g_off[n] = off;
    g_w[n]   = make_float4(w00, w01, w10, w11);
}

// ---------------------------------------------------------------------------
// Kernel A: fused transpose + voxel copy + meta (all independent work).
// ---------------------------------------------------------------------------
__global__ __launch_bounds__(256)
void prep_kernel(const float* __restrict__ img,
                 const float* __restrict__ points_mean,
                 const int*   __restrict__ coors,
                 const float* __restrict__ lidar2img,
                 const int*   __restrict__ pad_shape,
                 const float* __restrict__ voxel_feats,
                 float*       __restrict__ out) {
    if (blockIdx.x < TR_BLOCKS) {
        transpose_tile(img, blockIdx.x, threadIdx.x);
    } else if (blockIdx.x < TR_BLOCKS + VOX_BLOCKS) {
        voxel_copy(voxel_feats, out, blockIdx.x - TR_BLOCKS, threadIdx.x);
    } else {
        const int n = (blockIdx.x - TR_BLOCKS - VOX_BLOCKS) * 256 + threadIdx.x;
        if (n < NPTS)
            meta_point(points_mean, coors, lidar2img, pad_shape, n);
    }
}

// Branchless corner accumulate (used ONLY inside the valid-point path, so
// invalid corners — offset 0, weight 0 — are rare and read a hot line).
// Straight-line code lets ptxas batch all corner LDG.128s of the point.
__device__ __forceinline__ void corner_acc(int off, float w,
                                           int off0, int off1,
                                           float4& a0, float4& a1) {
    const float* row = g_imgT + off;
    float4 v0 = *(const float4*)(row + off0);
    float4 v1 = *(const float4*)(row + off1);
    a0.x = fmaf(w, v0.x, a0.x); a0.y = fmaf(w, v0.y, a0.y);
    a0.z = fmaf(w, v0.z, a0.z); a0.w = fmaf(w, v0.w, a0.w);
    a1.x = fmaf(w, v1.x, a1.x); a1.y = fmaf(w, v1.y, a1.y);
    a1.z = fmaf(w, v1.z, a1.z); a1.w = fmaf(w, v1.w, a1.w);
}

// ---------------------------------------------------------------------------
// Kernel B: gather + point-feat write. Block owns 16 points; warp owns 2.
// ONE branch per point: if all 4 weights are zero (~85% of points, fully
// off-screen) skip every gather and store zeros; otherwise run the
// branchless 4-corner accumulate so all 8 LDG.128s batch for max MLP.
// ---------------------------------------------------------------------------
__global__ __launch_bounds__(256)
void gather_kernel(float* __restrict__ out) {
    __shared__ int4   s_off[PTS_PER_BLOCK];
    __shared__ float4 s_w[PTS_PER_BLOCK];

    const int t    = threadIdx.x;
    const int base = blockIdx.x * PTS_PER_BLOCK;

    if (t < PTS_PER_BLOCK) {
        s_off[t] = __ldg(&g_off[base + t]);
    } else if (t < 2 * PTS_PER_BLOCK) {
        s_w[t - PTS_PER_BLOCK] = __ldg(&g_w[base + t - PTS_PER_BLOCK]);
    }
    __syncthreads();

    const int warp = t >> 5;   // 0..7
    const int lane = t & 31;
    const int off0 = lane * 4;
    const int off1 = 128 + lane * 4;

    #pragma unroll
    for (int i = 0; i < 2; i++) {
        const int li = warp * 2 + i;   // 0..15
        const int n  = base + li;      // NPTS % 16 == 0 -> in bounds

        const int4   off = s_off[li];  // LDS broadcast
        const float4 w   = s_w[li];

        float4 a0 = make_float4(0.f, 0.f, 0.f, 0.f);
        float4 a1 = make_float4(0.f, 0.f, 0.f, 0.f);

        // weights are >= 0: sum == 0 <=> all corners invalid
        if ((w.x + w.y) + (w.z + w.w) != 0.0f) {
            corner_acc(off.x, w.x, off0, off1, a0, a1);
            corner_acc(off.y, w.y, off0, off1, a0, a1);
            corner_acc(off.z, w.z, off0, off1, a0, a1);
            corner_acc(off.w, w.w, off0, off1, a0, a1);
        }

        float4* orow = (float4*)(out + (size_t)n * OUTW);
        __stcs(&orow[16 + lane],      a0);
        __stcs(&orow[16 + 32 + lane], a1);
    }
}

// ---------------------------------------------------------------------------
extern "C" void kernel_launch(void* const* d_in, const int* in_sizes, int n_in,
                              void* d_out, int out_size) {
    const float* points_mean = (const float*)d_in[0];
    // d_in[1] = mask (unused by reference)
    const float* voxel_feats = (const float*)d_in[2];
    const int*   coors       = (const int*)  d_in[3];
    const float* img_feats   = (const float*)d_in[4];
    const float* lidar2img   = (const float*)d_in[5];
    const int*   pad_shape   = (const int*)  d_in[6];
    float*       out         = (float*)d_out;

    // A: fused transpose + voxel copy + projection meta
    prep_kernel<<<TR_BLOCKS + VOX_BLOCKS + META_BLOCKS, 256>>>(
        img_feats, points_mean, coors, lidar2img, pad_shape, voxel_feats, out);

    // B: gather + point-feat write (block = 16 points)
    gather_kernel<<<NPTS / PTS_PER_BLOCK, 256>>>(out);
}